// round 16
// baseline (speedup 1.0000x reference)
#include <cuda_runtime.h>
#include <math.h>

#define NQ    13
#define QDIM  8192
#define NT    512
#define NLAY  5                  /* DEPTH+1 */
#define S13   0.0001220703125f   /* 2^-13: DIM^-1/2 * fwht norm folded */
#define PI_F  3.14159265358979323846f

#ifndef USE_TF32
#define USE_TF32 0
#endif

static __device__ __forceinline__ float tf32r(float x){
#if USE_TF32
    unsigned u;
    asm("cvt.rna.tf32.f32 %0, %1;" : "=r"(u) : "f"(x));
    return __uint_as_float(u);
#else
    return x;
#endif
}

/* Rz(b)*Ry(a) on an amplitude pair (z0 = qubit-bit 0).  Identical math to
   the passing R9 kernel. */
static __device__ __forceinline__ void rot1(float2& z0, float2& z1,
                                            float ca, float sa, float cb, float sb){
    float t0r = fmaf(ca, z0.x, -sa * z1.x);
    float t0i = fmaf(ca, z0.y, -sa * z1.y);
    float t1r = fmaf(sa, z0.x,  ca * z1.x);
    float t1i = fmaf(sa, z0.y,  ca * z1.y);
    z0.x = fmaf(cb, t0r,  sb * t0i);
    z0.y = fmaf(cb, t0i, -sb * t0r);
    z1.x = fmaf(cb, t1r, -sb * t1i);
    z1.y = fmaf(cb, t1i,  sb * t1r);
}

/* gate on register bit K (pairs inside the 16-amp register file) */
template<int K>
static __device__ __forceinline__ void regGate(float2* R, const float* g){
    const float ca = g[0], sa = g[1], cb = g[2], sb = g[3];
#pragma unroll
    for (int m = 0; m < 8; m++){
        int i0 = ((m >> K) << (K + 1)) | (m & ((1 << K) - 1));
        rot1(R[i0], R[i0 | (1 << K)], ca, sa, cb, sb);
    }
}

/* Hadamard butterfly on register bit K (unnormalized) */
template<int K>
static __device__ __forceinline__ void regH(float2* R){
#pragma unroll
    for (int m = 0; m < 8; m++){
        int i0 = ((m >> K) << (K + 1)) | (m & ((1 << K) - 1));
        int i1 = i0 | (1 << K);
        float2 a = R[i0], b = R[i1];
        R[i0] = make_float2(a.x + b.x, a.y + b.y);
        R[i1] = make_float2(a.x - b.x, a.y - b.y);
    }
}

/* gate on lane bit K: partner via shfl_xor; thread with bit=0 computes the
   z0 output row, bit=1 the z1 row (sign-selected coefficients). */
template<int K>
static __device__ __forceinline__ void shflGate(float2* R, int lane, const float* g){
    const float ca = g[0], sa = g[1], cb = g[2], sb = g[3];
    const bool  b  = (lane >> K) & 1;
    const float s  = b ?  sa : -sa;
    const float si = b ?  sb : -sb;
#pragma unroll
    for (int r = 0; r < 16; r++){
        float ox = __shfl_xor_sync(0xFFFFFFFFu, R[r].x, 1 << K);
        float oy = __shfl_xor_sync(0xFFFFFFFFu, R[r].y, 1 << K);
        float tx = fmaf(ca, R[r].x, s * ox);
        float ty = fmaf(ca, R[r].y, s * oy);
        R[r].x = fmaf(cb, tx, -si * ty);
        R[r].y = fmaf(si, tx,  cb * ty);
    }
}

/* Hadamard butterfly on lane bit K */
template<int K>
static __device__ __forceinline__ void shflH(float2* R, int lane){
    const float s = ((lane >> K) & 1) ? -1.f : 1.f;
#pragma unroll
    for (int r = 0; r < 16; r++){
        float ox = __shfl_xor_sync(0xFFFFFFFFu, R[r].x, 1 << K);
        float oy = __shfl_xor_sync(0xFFFFFFFFu, R[r].y, 1 << K);
        R[r].x = fmaf(s, R[r].x, ox);
        R[r].y = fmaf(s, R[r].y, oy);
    }
}

/* ---- smem exchange: storage swizzle L(e) = (e&~15) | ((e&15) ^ sig(e>>4)),
   sig(h) = (h ^ (h>>4)) & 15.  Conflict-free for all four patterns below. ---- */

/* layout A: e = (tid<<4) | r */
static __device__ __forceinline__ void storeA(float* re, float* im, const float2* R, int tid){
    const int sw = (tid ^ (tid >> 4)) & 15;
    const int base = tid << 4;
#pragma unroll
    for (int r = 0; r < 16; r++){
        int L = base | (r ^ sw);
        re[L] = R[r].x; im[L] = R[r].y;
    }
}
static __device__ __forceinline__ void loadA(const float* re, const float* im, float2* R, int tid){
    const int sw = (tid ^ (tid >> 4)) & 15;
    const int base = tid << 4;
#pragma unroll
    for (int r = 0; r < 16; r++){
        int L = base | (r ^ sw);
        R[r].x = re[L]; R[r].y = im[L];
    }
}
/* layout B: e = (r<<9) | tid ;  sig = ((tid>>4) ^ (tid>>8) ^ (r<<1)) & 15 */
static __device__ __forceinline__ void storeB(float* re, float* im, const float2* R, int tid){
    const int hb = tid & 0x1F0, lo = tid & 15;
    const int s0 = ((tid >> 4) ^ (tid >> 8)) & 15;
#pragma unroll
    for (int r = 0; r < 16; r++){
        int L = (r << 9) | hb | (lo ^ ((s0 ^ (r << 1)) & 15));
        re[L] = R[r].x; im[L] = R[r].y;
    }
}
static __device__ __forceinline__ void loadB(const float* re, const float* im, float2* R, int tid){
    const int hb = tid & 0x1F0, lo = tid & 15;
    const int s0 = ((tid >> 4) ^ (tid >> 8)) & 15;
#pragma unroll
    for (int r = 0; r < 16; r++){
        int L = (r << 9) | hb | (lo ^ ((s0 ^ (r << 1)) & 15));
        R[r].x = re[L]; R[r].y = im[L];
    }
}

/* CZ-chain diagonal: sign = (-1)^popc(e & (e>>1)) */
static __device__ __forceinline__ void entAt(float2* R, int e_of_r[16]){
#pragma unroll
    for (int r = 0; r < 16; r++){
        int e = e_of_r[r];
        if (__popc(e & (e >> 1)) & 1){ R[r].x = -R[r].x; R[r].y = -R[r].y; }
    }
}

__global__ void __launch_bounds__(NT)
QubitClassifier_66975720014174_kernel(const float* __restrict__ x,
                                      const float* __restrict__ theta,
                                      const float* __restrict__ bias,
                                      float* __restrict__ out)
{
    extern __shared__ float sm[];
    float* re  = sm;                 /* 8192 */
    float* im  = re  + QDIM;         /* 8192 */
    float* gst = im  + QDIM;         /* 65 gates x 4 = 260 */
    float* xs  = gst + 4 * NLAY * NQ;/* 13 */
    float* asv = xs  + NQ;           /* 13 */
    float* duA = asv + NQ;           /* 16 */
    float* dvA = duA + 16;           /* 16 */
    float* duB = dvA + 16;           /* 16 */
    float* dvB = duB + 16;           /* 16 */
    float* red = dvB + 16;           /* 16 warp partials */

    const int tid  = threadIdx.x;
    const int lane = tid & 31;
    const float* xr = x + (size_t)blockIdx.x * NQ;

    /* ---- per-CTA setup ---- */
    if (tid < NLAY * NQ){
        float al = theta[2 * tid];
        float be = theta[2 * tid + 1];
        gst[4 * tid + 0] = cosf(0.5f * al);
        gst[4 * tid + 1] = sinf(0.5f * al);
        gst[4 * tid + 2] = cosf(0.5f * be);
        gst[4 * tid + 3] = sinf(0.5f * be);
    }
    if (tid < NQ){
        float xv = xr[tid];
        xs[tid]  = tf32r(xv);
        asv[tid] = tf32r(PI_F - xv);
    }
    if (tid < 16){               /* layout-A deltas: qubits 9..12, sign from r bit (12-q) */
        float du = 0.f, dv = 0.f;
#pragma unroll
        for (int q = 9; q < 13; q++){
            float sg = ((tid >> (12 - q)) & 1) ? -1.f : 1.f;
            du = fmaf(sg, tf32r(xr[q]),        du);
            dv = fmaf(sg, tf32r(PI_F - xr[q]), dv);
        }
        duA[tid] = du; dvA[tid] = dv;
    } else if (tid < 32){        /* layout-B deltas: qubits 0..3, sign from r bit (3-q) */
        int r = tid - 16;
        float du = 0.f, dv = 0.f;
#pragma unroll
        for (int q = 0; q < 4; q++){
            float sg = ((r >> (3 - q)) & 1) ? -1.f : 1.f;
            du = fmaf(sg, tf32r(xr[q]),        du);
            dv = fmaf(sg, tf32r(PI_F - xr[q]), dv);
        }
        duB[r] = du; dvB[r] = dv;
    }
    float asq = 0.f;             /* elementwise reduce in ref: plain fp32 */
#pragma unroll
    for (int j = 0; j < NQ; j++){
        float af = PI_F - xr[j];
        asq = fmaf(af, af, asq);
    }
    __syncthreads();

    float2 R[16];

    /* ---- init, layout A: e = (tid<<4)|r ; psi = exp(i*phi(e)) * 2^-13 ---- */
    {
        float ub = 0.f, vb = 0.f;          /* qubits 0..8 from tid bits 8..0 */
#pragma unroll
        for (int q = 0; q < 9; q++){
            float sg = ((tid >> (8 - q)) & 1) ? -1.f : 1.f;
            ub = fmaf(sg, xs[q],  ub);
            vb = fmaf(sg, asv[q], vb);
        }
#pragma unroll
        for (int r = 0; r < 16; r++){
            float u = ub + duA[r];
            float v = vb + dvA[r];
            float phi = u + 0.5f * fmaf(v, v, -asq);
            float sn, cs; sincosf(phi, &sn, &cs);
            R[r] = make_float2(cs * S13, sn * S13);
        }
    }

    /* ---- FWHT: reg bits 0-3, lane bits 4-8, exchange, reg bits 9-12 ---- */
    regH<0>(R); regH<1>(R); regH<2>(R); regH<3>(R);
    shflH<0>(R, lane); shflH<1>(R, lane); shflH<2>(R, lane);
    shflH<3>(R, lane); shflH<4>(R, lane);
    storeA(re, im, R, tid); __syncthreads();
    loadB(re, im, R, tid);  __syncthreads();
    regH<0>(R); regH<1>(R); regH<2>(R); regH<3>(R);
    /* now layout B: e = (r<<9)|tid */

    /* ---- second feature-map diagonal, layout B ---- */
    {
        float ub = 0.f, vb = 0.f;          /* qubits 4..12 from tid bits 8..0 */
#pragma unroll
        for (int q = 4; q < 13; q++){
            float sg = ((tid >> (12 - q)) & 1) ? -1.f : 1.f;
            ub = fmaf(sg, xs[q],  ub);
            vb = fmaf(sg, asv[q], vb);
        }
#pragma unroll
        for (int r = 0; r < 16; r++){
            float u = ub + duB[r];
            float v = vb + dvB[r];
            float phi = u + 0.5f * fmaf(v, v, -asq);
            float sn, cs; sincosf(phi, &sn, &cs);
            float zr = R[r].x, zi = R[r].y;
            R[r].x = fmaf(zr, cs, -zi * sn);
            R[r].y = fmaf(zr, sn,  zi * cs);
        }
    }

    /* layout B: reg bit k <-> qubit 3-k ; lane bit k <-> qubit 12-k
       layout A: reg bit k <-> qubit 12-k ; lane bit k <-> qubit 8-k   */
#define LAYER_FROM_B(G)                                                       \
    do{                                                                       \
        regGate<0>(R, (G) + 4*3);  regGate<1>(R, (G) + 4*2);                  \
        regGate<2>(R, (G) + 4*1);  regGate<3>(R, (G) + 4*0);                  \
        shflGate<0>(R, lane, (G) + 4*12); shflGate<1>(R, lane, (G) + 4*11);   \
        shflGate<2>(R, lane, (G) + 4*10); shflGate<3>(R, lane, (G) + 4*9);    \
        shflGate<4>(R, lane, (G) + 4*8);                                      \
        storeB(re, im, R, tid); __syncthreads();                              \
        loadA(re, im, R, tid);  __syncthreads();                              \
        shflGate<1>(R, lane, (G) + 4*7);  shflGate<2>(R, lane, (G) + 4*6);    \
        shflGate<3>(R, lane, (G) + 4*5);  shflGate<4>(R, lane, (G) + 4*4);    \
    }while(0)

#define LAYER_FROM_A(G)                                                       \
    do{                                                                       \
        regGate<0>(R, (G) + 4*12); regGate<1>(R, (G) + 4*11);                 \
        regGate<2>(R, (G) + 4*10); regGate<3>(R, (G) + 4*9);                  \
        shflGate<0>(R, lane, (G) + 4*8);  shflGate<1>(R, lane, (G) + 4*7);    \
        shflGate<2>(R, lane, (G) + 4*6);  shflGate<3>(R, lane, (G) + 4*5);    \
        shflGate<4>(R, lane, (G) + 4*4);                                      \
        storeA(re, im, R, tid); __syncthreads();                              \
        loadB(re, im, R, tid);  __syncthreads();                              \
        regGate<0>(R, (G) + 4*3);  regGate<1>(R, (G) + 4*2);                  \
        regGate<2>(R, (G) + 4*1);  regGate<3>(R, (G) + 4*0);                  \
    }while(0)

    int eA[16], eB[16];
#pragma unroll
    for (int r = 0; r < 16; r++){ eA[r] = (tid << 4) | r; eB[r] = (r << 9) | tid; }

    /* layer 0: entry layout B (diag d already applied) -> ends A */
    LAYER_FROM_B(gst + 0 * 4 * NQ);
    /* layer 1: ENT in A, A-start -> ends B */
    entAt(R, eA);
    LAYER_FROM_A(gst + 1 * 4 * NQ);
    /* layer 2: ENT in B, B-start -> ends A */
    entAt(R, eB);
    LAYER_FROM_B(gst + 2 * 4 * NQ);
    /* layer 3: ENT in A, A-start -> ends B */
    entAt(R, eA);
    LAYER_FROM_A(gst + 3 * 4 * NQ);
    /* layer 4: ENT in B, B-start -> ends A */
    entAt(R, eB);
    LAYER_FROM_B(gst + 4 * 4 * NQ);

    /* ---- parity-weighted probability reduction (layout A) ---- */
    float acc = 0.f;
    const int stp = __popc(tid) & 1;
#pragma unroll
    for (int r = 0; r < 16; r++){
        float pr = fmaf(R[r].x, R[r].x, R[r].y * R[r].y);
        acc += ((stp ^ (__popc(r) & 1)) ? -pr : pr);
    }
#pragma unroll
    for (int o = 16; o > 0; o >>= 1)
        acc += __shfl_xor_sync(0xFFFFFFFFu, acc, o);
    if (lane == 0) red[tid >> 5] = acc;
    __syncthreads();
    if (tid < 32){
        float v = (tid < NT / 32) ? red[tid] : 0.f;
#pragma unroll
        for (int o = 8; o > 0; o >>= 1)
            v += __shfl_xor_sync(0xFFFFFFFFu, v, o);
        if (tid == 0){
            float logit = v + bias[0];
            out[2 * blockIdx.x + 0] = -logit;
            out[2 * blockIdx.x + 1] =  logit;
        }
    }
}

extern "C" void kernel_launch(void* const* d_in, const int* in_sizes, int n_in,
                              void* d_out, int out_size)
{
    const float* x     = (const float*)d_in[0];
    const float* theta = (const float*)d_in[1];
    const float* bias  = (const float*)d_in[2];
    float*       out   = (float*)d_out;

    const int B = in_sizes[0] / NQ;   /* 512 */
    const int smem_bytes = (2 * QDIM + 4 * NLAY * NQ + 2 * NQ + 4 * 16 + 16)
                           * (int)sizeof(float);

    cudaFuncSetAttribute(QubitClassifier_66975720014174_kernel,
                         cudaFuncAttributeMaxDynamicSharedMemorySize, smem_bytes);
    QubitClassifier_66975720014174_kernel<<<B, NT, smem_bytes>>>(x, theta, bias, out);
}

// round 17
// speedup vs baseline: 1.0116x; 1.0116x over previous
#include <cuda_runtime.h>
#include <math.h>

#define NQ    13
#define QDIM  8192
#define NT    512
#define NLAY  5                  /* DEPTH+1 */
#define S13   0.0001220703125f   /* 2^-13: DIM^-1/2 * fwht norm folded */
#define PI_F  3.14159265358979323846f

#ifndef USE_TF32
#define USE_TF32 0
#endif

static __device__ __forceinline__ float tf32r(float x){
#if USE_TF32
    unsigned u;
    asm("cvt.rna.tf32.f32 %0, %1;" : "=r"(u) : "f"(x));
    return __uint_as_float(u);
#else
    return x;
#endif
}

/* Rz(b)*Ry(a) on an amplitude pair (z0 = qubit-bit 0).  Identical math to
   the passing R9 kernel. */
static __device__ __forceinline__ void rot1(float2& z0, float2& z1,
                                            float ca, float sa, float cb, float sb){
    float t0r = fmaf(ca, z0.x, -sa * z1.x);
    float t0i = fmaf(ca, z0.y, -sa * z1.y);
    float t1r = fmaf(sa, z0.x,  ca * z1.x);
    float t1i = fmaf(sa, z0.y,  ca * z1.y);
    z0.x = fmaf(cb, t0r,  sb * t0i);
    z0.y = fmaf(cb, t0i, -sb * t0r);
    z1.x = fmaf(cb, t1r, -sb * t1i);
    z1.y = fmaf(cb, t1i,  sb * t1r);
}

/* gate on register bit K (pairs inside the 16-amp register file) */
template<int K>
static __device__ __forceinline__ void regGate(float2* R, const float* g){
    const float ca = g[0], sa = g[1], cb = g[2], sb = g[3];
#pragma unroll
    for (int m = 0; m < 8; m++){
        int i0 = ((m >> K) << (K + 1)) | (m & ((1 << K) - 1));
        rot1(R[i0], R[i0 | (1 << K)], ca, sa, cb, sb);
    }
}

/* Hadamard butterfly on register bit K (unnormalized) */
template<int K>
static __device__ __forceinline__ void regH(float2* R){
#pragma unroll
    for (int m = 0; m < 8; m++){
        int i0 = ((m >> K) << (K + 1)) | (m & ((1 << K) - 1));
        int i1 = i0 | (1 << K);
        float2 a = R[i0], b = R[i1];
        R[i0] = make_float2(a.x + b.x, a.y + b.y);
        R[i1] = make_float2(a.x - b.x, a.y - b.y);
    }
}

/* gate on lane bit K: partner via shfl_xor; thread with bit=0 computes the
   z0 output row, bit=1 the z1 row (sign-selected coefficients). */
template<int K>
static __device__ __forceinline__ void shflGate(float2* R, int lane, const float* g){
    const float ca = g[0], sa = g[1], cb = g[2], sb = g[3];
    const bool  b  = (lane >> K) & 1;
    const float s  = b ?  sa : -sa;
    const float si = b ?  sb : -sb;
#pragma unroll
    for (int r = 0; r < 16; r++){
        float ox = __shfl_xor_sync(0xFFFFFFFFu, R[r].x, 1 << K);
        float oy = __shfl_xor_sync(0xFFFFFFFFu, R[r].y, 1 << K);
        float tx = fmaf(ca, R[r].x, s * ox);
        float ty = fmaf(ca, R[r].y, s * oy);
        R[r].x = fmaf(cb, tx, -si * ty);
        R[r].y = fmaf(si, tx,  cb * ty);
    }
}

/* Hadamard butterfly on lane bit K */
template<int K>
static __device__ __forceinline__ void shflH(float2* R, int lane){
    const float s = ((lane >> K) & 1) ? -1.f : 1.f;
#pragma unroll
    for (int r = 0; r < 16; r++){
        float ox = __shfl_xor_sync(0xFFFFFFFFu, R[r].x, 1 << K);
        float oy = __shfl_xor_sync(0xFFFFFFFFu, R[r].y, 1 << K);
        R[r].x = fmaf(s, R[r].x, ox);
        R[r].y = fmaf(s, R[r].y, oy);
    }
}

/* ---- smem exchange: storage swizzle L(e) = (e&~15) | ((e&15) ^ sig(e>>4)),
   sig(h) = (h ^ (h>>4)) & 15.  Conflict-free for all four patterns below. ---- */

/* layout A: e = (tid<<4) | r */
static __device__ __forceinline__ void storeA(float* re, float* im, const float2* R, int tid){
    const int sw = (tid ^ (tid >> 4)) & 15;
    const int base = tid << 4;
#pragma unroll
    for (int r = 0; r < 16; r++){
        int L = base | (r ^ sw);
        re[L] = R[r].x; im[L] = R[r].y;
    }
}
static __device__ __forceinline__ void loadA(const float* re, const float* im, float2* R, int tid){
    const int sw = (tid ^ (tid >> 4)) & 15;
    const int base = tid << 4;
#pragma unroll
    for (int r = 0; r < 16; r++){
        int L = base | (r ^ sw);
        R[r].x = re[L]; R[r].y = im[L];
    }
}
/* layout B: e = (r<<9) | tid ;  sig = ((tid>>4) ^ (tid>>8) ^ (r<<1)) & 15 */
static __device__ __forceinline__ void storeB(float* re, float* im, const float2* R, int tid){
    const int hb = tid & 0x1F0, lo = tid & 15;
    const int s0 = ((tid >> 4) ^ (tid >> 8)) & 15;
#pragma unroll
    for (int r = 0; r < 16; r++){
        int L = (r << 9) | hb | (lo ^ ((s0 ^ (r << 1)) & 15));
        re[L] = R[r].x; im[L] = R[r].y;
    }
}
static __device__ __forceinline__ void loadB(const float* re, const float* im, float2* R, int tid){
    const int hb = tid & 0x1F0, lo = tid & 15;
    const int s0 = ((tid >> 4) ^ (tid >> 8)) & 15;
#pragma unroll
    for (int r = 0; r < 16; r++){
        int L = (r << 9) | hb | (lo ^ ((s0 ^ (r << 1)) & 15));
        R[r].x = re[L]; R[r].y = im[L];
    }
}

/* CZ-chain diagonal: sign = (-1)^popc(e & (e>>1)) */
static __device__ __forceinline__ void entAt(float2* R, int e_of_r[16]){
#pragma unroll
    for (int r = 0; r < 16; r++){
        int e = e_of_r[r];
        if (__popc(e & (e >> 1)) & 1){ R[r].x = -R[r].x; R[r].y = -R[r].y; }
    }
}

__global__ void __launch_bounds__(NT)
QubitClassifier_66975720014174_kernel(const float* __restrict__ x,
                                      const float* __restrict__ theta,
                                      const float* __restrict__ bias,
                                      float* __restrict__ out)
{
    extern __shared__ float sm[];
    float* re  = sm;                 /* 8192 */
    float* im  = re  + QDIM;         /* 8192 */
    float* gst = im  + QDIM;         /* 65 gates x 4 = 260 */
    float* xs  = gst + 4 * NLAY * NQ;/* 13 */
    float* asv = xs  + NQ;           /* 13 */
    float* duA = asv + NQ;           /* 16 */
    float* dvA = duA + 16;           /* 16 */
    float* duB = dvA + 16;           /* 16 */
    float* dvB = duB + 16;           /* 16 */
    float* red = dvB + 16;           /* 16 warp partials */

    const int tid  = threadIdx.x;
    const int lane = tid & 31;
    const float* xr = x + (size_t)blockIdx.x * NQ;

    /* ---- per-CTA setup ---- */
    if (tid < NLAY * NQ){
        float al = theta[2 * tid];
        float be = theta[2 * tid + 1];
        gst[4 * tid + 0] = cosf(0.5f * al);
        gst[4 * tid + 1] = sinf(0.5f * al);
        gst[4 * tid + 2] = cosf(0.5f * be);
        gst[4 * tid + 3] = sinf(0.5f * be);
    }
    if (tid < NQ){
        float xv = xr[tid];
        xs[tid]  = tf32r(xv);
        asv[tid] = tf32r(PI_F - xv);
    }
    if (tid < 16){               /* layout-A deltas: qubits 9..12, sign from r bit (12-q) */
        float du = 0.f, dv = 0.f;
#pragma unroll
        for (int q = 9; q < 13; q++){
            float sg = ((tid >> (12 - q)) & 1) ? -1.f : 1.f;
            du = fmaf(sg, tf32r(xr[q]),        du);
            dv = fmaf(sg, tf32r(PI_F - xr[q]), dv);
        }
        duA[tid] = du; dvA[tid] = dv;
    } else if (tid < 32){        /* layout-B deltas: qubits 0..3, sign from r bit (3-q) */
        int r = tid - 16;
        float du = 0.f, dv = 0.f;
#pragma unroll
        for (int q = 0; q < 4; q++){
            float sg = ((r >> (3 - q)) & 1) ? -1.f : 1.f;
            du = fmaf(sg, tf32r(xr[q]),        du);
            dv = fmaf(sg, tf32r(PI_F - xr[q]), dv);
        }
        duB[r] = du; dvB[r] = dv;
    }
    float asq = 0.f;             /* elementwise reduce in ref: plain fp32 */
#pragma unroll
    for (int j = 0; j < NQ; j++){
        float af = PI_F - xr[j];
        asq = fmaf(af, af, asq);
    }
    __syncthreads();

    float2 R[16];

    /* ---- init, layout A: e = (tid<<4)|r ; psi = exp(i*phi(e)) * 2^-13 ---- */
    {
        float ub = 0.f, vb = 0.f;          /* qubits 0..8 from tid bits 8..0 */
#pragma unroll
        for (int q = 0; q < 9; q++){
            float sg = ((tid >> (8 - q)) & 1) ? -1.f : 1.f;
            ub = fmaf(sg, xs[q],  ub);
            vb = fmaf(sg, asv[q], vb);
        }
#pragma unroll
        for (int r = 0; r < 16; r++){
            float u = ub + duA[r];
            float v = vb + dvA[r];
            float phi = u + 0.5f * fmaf(v, v, -asq);
            float sn, cs; sincosf(phi, &sn, &cs);
            R[r] = make_float2(cs * S13, sn * S13);
        }
    }

    /* ---- FWHT: reg bits 0-3, lane bits 4-8, exchange, reg bits 9-12 ---- */
    regH<0>(R); regH<1>(R); regH<2>(R); regH<3>(R);
    shflH<0>(R, lane); shflH<1>(R, lane); shflH<2>(R, lane);
    shflH<3>(R, lane); shflH<4>(R, lane);
    storeA(re, im, R, tid); __syncthreads();
    loadB(re, im, R, tid);  __syncthreads();
    regH<0>(R); regH<1>(R); regH<2>(R); regH<3>(R);
    /* now layout B: e = (r<<9)|tid */

    /* ---- second feature-map diagonal, layout B ---- */
    {
        float ub = 0.f, vb = 0.f;          /* qubits 4..12 from tid bits 8..0 */
#pragma unroll
        for (int q = 4; q < 13; q++){
            float sg = ((tid >> (12 - q)) & 1) ? -1.f : 1.f;
            ub = fmaf(sg, xs[q],  ub);
            vb = fmaf(sg, asv[q], vb);
        }
#pragma unroll
        for (int r = 0; r < 16; r++){
            float u = ub + duB[r];
            float v = vb + dvB[r];
            float phi = u + 0.5f * fmaf(v, v, -asq);
            float sn, cs; sincosf(phi, &sn, &cs);
            float zr = R[r].x, zi = R[r].y;
            R[r].x = fmaf(zr, cs, -zi * sn);
            R[r].y = fmaf(zr, sn,  zi * cs);
        }
    }

    /* layout B: reg bit k <-> qubit 3-k ; lane bit k <-> qubit 12-k
       layout A: reg bit k <-> qubit 12-k ; lane bit k <-> qubit 8-k   */
#define LAYER_FROM_B(G)                                                       \
    do{                                                                       \
        regGate<0>(R, (G) + 4*3);  regGate<1>(R, (G) + 4*2);                  \
        regGate<2>(R, (G) + 4*1);  regGate<3>(R, (G) + 4*0);                  \
        shflGate<0>(R, lane, (G) + 4*12); shflGate<1>(R, lane, (G) + 4*11);   \
        shflGate<2>(R, lane, (G) + 4*10); shflGate<3>(R, lane, (G) + 4*9);    \
        shflGate<4>(R, lane, (G) + 4*8);                                      \
        storeB(re, im, R, tid); __syncthreads();                              \
        loadA(re, im, R, tid);  __syncthreads();                              \
        shflGate<1>(R, lane, (G) + 4*7);  shflGate<2>(R, lane, (G) + 4*6);    \
        shflGate<3>(R, lane, (G) + 4*5);  shflGate<4>(R, lane, (G) + 4*4);    \
    }while(0)

#define LAYER_FROM_A(G)                                                       \
    do{                                                                       \
        regGate<0>(R, (G) + 4*12); regGate<1>(R, (G) + 4*11);                 \
        regGate<2>(R, (G) + 4*10); regGate<3>(R, (G) + 4*9);                  \
        shflGate<0>(R, lane, (G) + 4*8);  shflGate<1>(R, lane, (G) + 4*7);    \
        shflGate<2>(R, lane, (G) + 4*6);  shflGate<3>(R, lane, (G) + 4*5);    \
        shflGate<4>(R, lane, (G) + 4*4);                                      \
        storeA(re, im, R, tid); __syncthreads();                              \
        loadB(re, im, R, tid);  __syncthreads();                              \
        regGate<0>(R, (G) + 4*3);  regGate<1>(R, (G) + 4*2);                  \
        regGate<2>(R, (G) + 4*1);  regGate<3>(R, (G) + 4*0);                  \
    }while(0)

    int eA[16], eB[16];
#pragma unroll
    for (int r = 0; r < 16; r++){ eA[r] = (tid << 4) | r; eB[r] = (r << 9) | tid; }

    /* layer 0: entry layout B (diag d already applied) -> ends A */
    LAYER_FROM_B(gst + 0 * 4 * NQ);
    /* layer 1: ENT in A, A-start -> ends B */
    entAt(R, eA);
    LAYER_FROM_A(gst + 1 * 4 * NQ);
    /* layer 2: ENT in B, B-start -> ends A */
    entAt(R, eB);
    LAYER_FROM_B(gst + 2 * 4 * NQ);
    /* layer 3: ENT in A, A-start -> ends B */
    entAt(R, eA);
    LAYER_FROM_A(gst + 3 * 4 * NQ);
    /* layer 4: ENT in B, B-start -> ends A */
    entAt(R, eB);
    LAYER_FROM_B(gst + 4 * 4 * NQ);

    /* ---- parity-weighted probability reduction (layout A) ---- */
    float acc = 0.f;
    const int stp = __popc(tid) & 1;
#pragma unroll
    for (int r = 0; r < 16; r++){
        float pr = fmaf(R[r].x, R[r].x, R[r].y * R[r].y);
        acc += ((stp ^ (__popc(r) & 1)) ? -pr : pr);
    }
#pragma unroll
    for (int o = 16; o > 0; o >>= 1)
        acc += __shfl_xor_sync(0xFFFFFFFFu, acc, o);
    if (lane == 0) red[tid >> 5] = acc;
    __syncthreads();
    if (tid < 32){
        float v = (tid < NT / 32) ? red[tid] : 0.f;
#pragma unroll
        for (int o = 8; o > 0; o >>= 1)
            v += __shfl_xor_sync(0xFFFFFFFFu, v, o);
        if (tid == 0){
            float logit = v + bias[0];
            out[2 * blockIdx.x + 0] = -logit;
            out[2 * blockIdx.x + 1] =  logit;
        }
    }
}

extern "C" void kernel_launch(void* const* d_in, const int* in_sizes, int n_in,
                              void* d_out, int out_size)
{
    const float* x     = (const float*)d_in[0];
    const float* theta = (const float*)d_in[1];
    const float* bias  = (const float*)d_in[2];
    float*       out   = (float*)d_out;

    const int B = in_sizes[0] / NQ;   /* 512 */
    const int smem_bytes = (2 * QDIM + 4 * NLAY * NQ + 2 * NQ + 4 * 16 + 16)
                           * (int)sizeof(float);

    cudaFuncSetAttribute(QubitClassifier_66975720014174_kernel,
                         cudaFuncAttributeMaxDynamicSharedMemorySize, smem_bytes);
    QubitClassifier_66975720014174_kernel<<<B, NT, smem_bytes>>>(x, theta, bias, out);
}